// round 15
// baseline (speedup 1.0000x reference)
#include <cuda_runtime.h>
#include <cuda_fp16.h>
#include <cstdint>

// out[b,u] = ||x_b||^2 - 2 * (x@w)[b,u] + ||w_u||^2
// x: [65536,256] f32, w: [256,1024] f32, out: [65536,1024] f32
//
// R14 (fp16/f16-accum, proven) with ONE parameter change: CTA widened to
// 256 threads / 8 warps, CTA tile 128b x 256u (warp tile still 64x64, 2x4
// grid), 2 CTAs/SM -> 16 warps/SM (vs 12). f16 accumulators freed the
// registers (acc=64) to fit the 128-reg cap of launch_bounds(256,2).
// Same loop schedule, same swizzle, same per-MMA LDSM ratio.

#define B_DIM 65536
#define F_DIM 256
#define U_DIM 1024
#define TILE  128                 // b-tile height
#define UTILE 256                 // u-tile width
#define NB_TILES (B_DIM / TILE)   // 512
#define NU_TILES (U_DIM / UTILE)  // 4
#define NSLICE   74               // 4 * 74 = 296 = 148 SMs x 2 CTAs
#define GRID_CTAS (NU_TILES * NSLICE)
#define NS       2                // double buffer

__device__ __half g_xh[(size_t)B_DIM * F_DIM];  // 32 MB
__device__ __half g_wh[(size_t)F_DIM * U_DIM];  // 512 KB (L2-resident)
__device__ float g_xsq[B_DIM];
__device__ float g_wsq[U_DIM];

// smem: A ring 2x16KB | B ring 2x32KB | wsq 1KB => 99328 B (2 CTAs/SM)
#define SM_A    0
#define SM_B    (NS * 16384)                    // 32768
#define SM_WSQ  (SM_B + NS * 32768)             // 98304
#define SM_TOT  (SM_WSQ + 1024)

// ---------------------------------------------------------------- helpers
__device__ __forceinline__ uint32_t smem_u32(const void* p) {
    uint32_t a;
    asm("{ .reg .u64 t; cvta.to.shared.u64 t, %1; cvt.u32.u64 %0, t; }" : "=r"(a) : "l"(p));
    return a;
}
__device__ __forceinline__ void cp16(uint32_t dst, const void* src) {
    asm volatile("cp.async.cg.shared.global [%0], [%1], 16;"
                 :: "r"(dst), "l"(__cvta_generic_to_global(src)) : "memory");
}
#define CP_COMMIT() asm volatile("cp.async.commit_group;" ::: "memory")
#define CP_WAIT(N)  asm volatile("cp.async.wait_group %0;" :: "n"(N) : "memory")

__device__ __forceinline__ void ldm_x4(uint32_t& r0, uint32_t& r1, uint32_t& r2, uint32_t& r3,
                                       uint32_t addr) {
    asm volatile("ldmatrix.sync.aligned.m8n8.x4.shared.b16 {%0,%1,%2,%3}, [%4];"
                 : "=r"(r0), "=r"(r1), "=r"(r2), "=r"(r3) : "r"(addr));
}
__device__ __forceinline__ void ldm_x4_t(uint32_t& r0, uint32_t& r1, uint32_t& r2, uint32_t& r3,
                                         uint32_t addr) {
    asm volatile("ldmatrix.sync.aligned.m8n8.x4.trans.shared.b16 {%0,%1,%2,%3}, [%4];"
                 : "=r"(r0), "=r"(r1), "=r"(r2), "=r"(r3) : "r"(addr));
}
// fp16 inputs, fp16 accumulators (2 packed half2 D-regs)
__device__ __forceinline__ void mma_16816_f16(uint32_t* c, const uint32_t* a, const uint32_t* b) {
    asm volatile("mma.sync.aligned.m16n8k16.row.col.f16.f16.f16.f16 "
                 "{%0,%1}, {%2,%3,%4,%5}, {%6,%7}, {%0,%1};"
                 : "+r"(c[0]), "+r"(c[1])
                 : "r"(a[0]), "r"(a[1]), "r"(a[2]), "r"(a[3]), "r"(b[0]), "r"(b[1]));
}

// ---------------------------------------------------------------- fused prep
//   blocks [0, 4):            wsq (latency-bound, runs first)
//   blocks [4, 260):          w -> fp16
//   blocks [260, 8452):       x -> fp16 + row sumsq
#define WSQ_BLOCKS   (U_DIM / 256)          // 4
#define WPREP_BLOCKS 256
#define XPREP_BLOCKS 8192
__global__ __launch_bounds__(256) void prep_kernel(const float* __restrict__ x,
                                                   const float* __restrict__ w) {
    int blk = blockIdx.x;
    if (blk < WSQ_BLOCKS) {
        int u = blk * 256 + threadIdx.x;
        float s0 = 0.f, s1 = 0.f;
#pragma unroll 8
        for (int f = 0; f < F_DIM / 2; f++) {
            float v0 = w[(size_t)f * U_DIM + u];
            float v1 = w[(size_t)(f + F_DIM / 2) * U_DIM + u];
            s0 = fmaf(v0, v0, s0);
            s1 = fmaf(v1, v1, s1);
        }
        g_wsq[u] = s0 + s1;
    } else if (blk < WSQ_BLOCKS + WPREP_BLOCKS) {
        int i = (blk - WSQ_BLOCKS) * 256 + threadIdx.x;
        float4 v = reinterpret_cast<const float4*>(w)[i];
        __half2 p0 = __floats2half2_rn(v.x, v.y), p1 = __floats2half2_rn(v.z, v.w);
        uint2 u;
        u.x = *reinterpret_cast<uint32_t*>(&p0); u.y = *reinterpret_cast<uint32_t*>(&p1);
        reinterpret_cast<uint2*>(g_wh)[i] = u;
    } else {
        int row = (blk - WSQ_BLOCKS - WPREP_BLOCKS) * 8 + (threadIdx.x >> 5);
        int lane = threadIdx.x & 31;
        const float4* src = reinterpret_cast<const float4*>(x + (size_t)row * F_DIM);
        float4 a = src[lane], b = src[lane + 32];
        float s = a.x * a.x + a.y * a.y + a.z * a.z + a.w * a.w
                + b.x * b.x + b.y * b.y + b.z * b.z + b.w * b.w;
#pragma unroll
        for (int o = 16; o > 0; o >>= 1) s += __shfl_down_sync(0xffffffffu, s, o);
        if (lane == 0) g_xsq[row] = s;
        uint2* dst = reinterpret_cast<uint2*>(g_xh + (size_t)row * F_DIM);
        __half2 p0 = __floats2half2_rn(a.x, a.y), p1 = __floats2half2_rn(a.z, a.w);
        __half2 q0 = __floats2half2_rn(b.x, b.y), q1 = __floats2half2_rn(b.z, b.w);
        uint2 u0, u1;
        u0.x = *reinterpret_cast<uint32_t*>(&p0); u0.y = *reinterpret_cast<uint32_t*>(&p1);
        u1.x = *reinterpret_cast<uint32_t*>(&q0); u1.y = *reinterpret_cast<uint32_t*>(&q1);
        dst[lane] = u0; dst[lane + 32] = u1;
    }
}

// ---------------------------------------------------------------- GEMM
__global__ __launch_bounds__(256, 2)
void rbf_gemm_kernel(float* __restrict__ out) {
    extern __shared__ char smem[];
    const uint32_t sb = smem_u32(smem);
    const int tid = threadIdx.x, lane = tid & 31, wi = tid >> 5;  // 8 warps
    const int warp_m = wi & 1, warp_n = wi >> 1;                  // 2x4, tiles 64x64

    const int u_tile = blockIdx.x & 3;          // u fastest -> L2 sharing of x stream
    const int sidx = blockIdx.x >> 2;
    const int u0 = u_tile * UTILE;
    const int b_begin = (sidx * NB_TILES) / NSLICE;
    const int b_end = ((sidx + 1) * NB_TILES) / NSLICE;
    const int C = (b_end - b_begin) * 4;        // 64-wide k-chunks

    if (tid < 64) {
        float4 v = reinterpret_cast<const float4*>(g_wsq + u0)[tid];
        reinterpret_cast<float4*>(smem + SM_WSQ)[tid] = v;
    }

    // chunk loader: A = x[bt*128 .. +128, kc*64 .. +64]  (128 rows x 128B)
    //               B = w[kc*64 .. +64, u0 .. +256]      (64 rows x 512B)
    auto load_chunk = [&](int c) {
        int slot = c & 1, kc = c & 3, bt = b_begin + (c >> 2);
        uint32_t abuf = sb + SM_A + (uint32_t)(slot * 16384);
        size_t abase = ((size_t)bt * TILE) * F_DIM + (size_t)kc * 64;
        for (int i = tid; i < 1024; i += 256) {
            int r = i >> 3, cc = i & 7;   // 128 rows x 8 vecs (128B/row)
            cp16(abuf + (uint32_t)(r * 128 + ((cc ^ (r & 7)) << 4)),
                 g_xh + abase + (size_t)r * F_DIM + cc * 8);
        }
        uint32_t bbuf = sb + SM_B + (uint32_t)(slot * 32768);
        const char* bbase = (const char*)(g_wh + (size_t)kc * 64 * U_DIM + u0);
        for (int i = tid; i < 2048; i += 256) {
            int k = i >> 5, cc = i & 31;  // 64 k-rows x 32 vecs (512B/row)
            cp16(bbuf + (uint32_t)(k * 512 + ((cc ^ (k & 7)) << 4)),
                 bbase + (size_t)k * U_DIM * 2 + cc * 16);
        }
        CP_COMMIT();
    };

    load_chunk(0);

    uint32_t acc[4][8][2];   // packed half2 accumulators
    const int lr = lane & 15, lc = lane >> 4;
    const int g = lane >> 2, cq = (lane & 3) * 2;
    const float* ws = reinterpret_cast<const float*>(smem + SM_WSQ);

    for (int c = 0; c < C; c++) {
        const int kc = c & 3, slot = c & 1;
        CP_WAIT(0);               // chunk c fully resident
        __syncthreads();          // cross-thread visibility + c-1 slot free

        if (c + 1 < C) load_chunk(c + 1);   // into the slot consumed at c-1

        if (kc == 0) {
#pragma unroll
            for (int mt = 0; mt < 4; mt++)
#pragma unroll
                for (int nt = 0; nt < 8; nt++) {
                    acc[mt][nt][0] = 0u;
                    acc[mt][nt][1] = 0u;
                }
        }

        // ---- compute chunk c: 64 k, 4 k-steps, warp tile 64x64 ----
        const uint32_t abuf = sb + SM_A + (uint32_t)(slot * 16384);
        const uint32_t bbuf = sb + SM_B + (uint32_t)(slot * 32768);
#pragma unroll
        for (int kk = 0; kk < 64; kk += 16) {
            uint32_t a_frag[4][4];
#pragma unroll
            for (int mt = 0; mt < 4; mt++) {
                int r = warp_m * 64 + mt * 16 + lr;
                int cch = (kk >> 3) + lc;
                uint32_t addr = abuf + (uint32_t)(r * 128 + ((cch ^ (r & 7)) << 4));
                ldm_x4(a_frag[mt][0], a_frag[mt][1], a_frag[mt][2], a_frag[mt][3], addr);
            }
            uint32_t b_frag[8][2];
#pragma unroll
            for (int np = 0; np < 4; np++) {
                int krow = kk + lr;   // within-chunk k row (0..63)
                int cch = warp_n * 8 + np * 2 + lc;   // 16B vec index (0..31)
                uint32_t addr = bbuf + (uint32_t)(krow * 512 + ((cch ^ (krow & 7)) << 4));
                uint32_t r0, r1, r2, r3;
                ldm_x4_t(r0, r1, r2, r3, addr);
                b_frag[np * 2][0] = r0;     b_frag[np * 2][1] = r1;
                b_frag[np * 2 + 1][0] = r2; b_frag[np * 2 + 1][1] = r3;
            }
#pragma unroll
            for (int mt = 0; mt < 4; mt++)
#pragma unroll
                for (int nt = 0; nt < 8; nt++)
                    mma_16816_f16(acc[mt][nt], a_frag[mt], b_frag[nt]);
        }

        // ---- epilogue ----
        if (kc == 3) {
            int bt = b_begin + (c >> 2);
#pragma unroll
            for (int mt = 0; mt < 4; mt++) {
                int rloc = warp_m * 64 + mt * 16 + g;
                float xlo = __ldg(&g_xsq[bt * TILE + rloc]);
                float xhi = __ldg(&g_xsq[bt * TILE + rloc + 8]);
                size_t row_lo = (size_t)(bt * TILE + rloc) * U_DIM;
                size_t row_hi = row_lo + (size_t)8 * U_DIM;
#pragma unroll
                for (int nt = 0; nt < 8; nt++) {
                    int cloc = warp_n * 64 + nt * 8 + cq;   // 0..255
                    float w0 = ws[cloc], w1 = ws[cloc + 1];
                    float2 clo = __half22float2(*reinterpret_cast<__half2*>(&acc[mt][nt][0]));
                    float2 chi = __half22float2(*reinterpret_cast<__half2*>(&acc[mt][nt][1]));
                    float2 vlo, vhi;
                    vlo.x = fmaf(-2.f, clo.x, xlo + w0);
                    vlo.y = fmaf(-2.f, clo.y, xlo + w1);
                    vhi.x = fmaf(-2.f, chi.x, xhi + w0);
                    vhi.y = fmaf(-2.f, chi.y, xhi + w1);
                    __stcs(reinterpret_cast<float2*>(out + row_lo + u0 + cloc), vlo);
                    __stcs(reinterpret_cast<float2*>(out + row_hi + u0 + cloc), vhi);
                }
            }
        }
    }
}

extern "C" void kernel_launch(void* const* d_in, const int* in_sizes, int n_in,
                              void* d_out, int out_size) {
    const float* x = (const float*)d_in[0];
    const float* w = (const float*)d_in[1];
    float* out = (float*)d_out;

    cudaFuncSetAttribute(rbf_gemm_kernel, cudaFuncAttributeMaxDynamicSharedMemorySize, SM_TOT);

    prep_kernel<<<WSQ_BLOCKS + WPREP_BLOCKS + XPREP_BLOCKS, 256>>>(x, w);
    rbf_gemm_kernel<<<GRID_CTAS, 256, SM_TOT>>>(out);
}

// round 16
// speedup vs baseline: 1.0541x; 1.0541x over previous
#include <cuda_runtime.h>
#include <cuda_fp16.h>
#include <cstdint>

// out[b,u] = ||x_b||^2 - 2 * (x@w)[b,u] + ||w_u||^2
// x: [65536,256] f32, w: [256,1024] f32, out: [65536,1024] f32
//
// R14 (fp16/f16-accum, proven schedule) with the warp tile grown to 128x64
// (f16 acc = 128 regs makes it affordable). CTA tile 256b x 128u, 128 threads,
// 2x2 warp grid, 2 CTAs/SM. LDSM bytes per MMA drop 25% ((128+64)/(128*64)
// vs (64+64)/(64*64)) -- L1 was the binding pipe at 63.1% vs tensor 54.5%.
// Loop schedule / swizzle / double-buffer byte-identical to R14.

#define B_DIM 65536
#define F_DIM 256
#define U_DIM 1024
#define BTILE 256                 // b-tile height
#define UTILE 128                 // u-tile width
#define NB_TILES (B_DIM / BTILE)  // 256
#define NU_TILES (U_DIM / UTILE)  // 8
#define NSLICE   37               // 8 * 37 = 296 = 148 SMs x 2 CTAs
#define GRID_CTAS (NU_TILES * NSLICE)
#define NS       2                // double buffer

__device__ __half g_xh[(size_t)B_DIM * F_DIM];  // 32 MB
__device__ __half g_wh[(size_t)F_DIM * U_DIM];  // 512 KB (L2-resident)
__device__ float g_xsq[B_DIM];
__device__ float g_wsq[U_DIM];

// smem: A ring 2x32KB | B ring 2x16KB | wsq 512B => 98816 B (2 CTAs/SM)
#define SM_A    0
#define SM_B    (NS * 32768)                    // 65536
#define SM_WSQ  (SM_B + NS * 16384)             // 98304
#define SM_TOT  (SM_WSQ + 512)

// ---------------------------------------------------------------- helpers
__device__ __forceinline__ uint32_t smem_u32(const void* p) {
    uint32_t a;
    asm("{ .reg .u64 t; cvta.to.shared.u64 t, %1; cvt.u32.u64 %0, t; }" : "=r"(a) : "l"(p));
    return a;
}
__device__ __forceinline__ void cp16(uint32_t dst, const void* src) {
    asm volatile("cp.async.cg.shared.global [%0], [%1], 16;"
                 :: "r"(dst), "l"(__cvta_generic_to_global(src)) : "memory");
}
#define CP_COMMIT() asm volatile("cp.async.commit_group;" ::: "memory")
#define CP_WAIT(N)  asm volatile("cp.async.wait_group %0;" :: "n"(N) : "memory")

__device__ __forceinline__ void ldm_x4(uint32_t& r0, uint32_t& r1, uint32_t& r2, uint32_t& r3,
                                       uint32_t addr) {
    asm volatile("ldmatrix.sync.aligned.m8n8.x4.shared.b16 {%0,%1,%2,%3}, [%4];"
                 : "=r"(r0), "=r"(r1), "=r"(r2), "=r"(r3) : "r"(addr));
}
__device__ __forceinline__ void ldm_x4_t(uint32_t& r0, uint32_t& r1, uint32_t& r2, uint32_t& r3,
                                         uint32_t addr) {
    asm volatile("ldmatrix.sync.aligned.m8n8.x4.trans.shared.b16 {%0,%1,%2,%3}, [%4];"
                 : "=r"(r0), "=r"(r1), "=r"(r2), "=r"(r3) : "r"(addr));
}
// fp16 inputs, fp16 accumulators (2 packed half2 D-regs)
__device__ __forceinline__ void mma_16816_f16(uint32_t* c, const uint32_t* a, const uint32_t* b) {
    asm volatile("mma.sync.aligned.m16n8k16.row.col.f16.f16.f16.f16 "
                 "{%0,%1}, {%2,%3,%4,%5}, {%6,%7}, {%0,%1};"
                 : "+r"(c[0]), "+r"(c[1])
                 : "r"(a[0]), "r"(a[1]), "r"(a[2]), "r"(a[3]), "r"(b[0]), "r"(b[1]));
}

// ---------------------------------------------------------------- fused prep
//   blocks [0, 4):            wsq (latency-bound, runs first)
//   blocks [4, 260):          w -> fp16
//   blocks [260, 8452):       x -> fp16 + row sumsq
#define WSQ_BLOCKS   (U_DIM / 256)          // 4
#define WPREP_BLOCKS 256
#define XPREP_BLOCKS 8192
__global__ __launch_bounds__(256) void prep_kernel(const float* __restrict__ x,
                                                   const float* __restrict__ w) {
    int blk = blockIdx.x;
    if (blk < WSQ_BLOCKS) {
        int u = blk * 256 + threadIdx.x;
        float s0 = 0.f, s1 = 0.f;
#pragma unroll 8
        for (int f = 0; f < F_DIM / 2; f++) {
            float v0 = w[(size_t)f * U_DIM + u];
            float v1 = w[(size_t)(f + F_DIM / 2) * U_DIM + u];
            s0 = fmaf(v0, v0, s0);
            s1 = fmaf(v1, v1, s1);
        }
        g_wsq[u] = s0 + s1;
    } else if (blk < WSQ_BLOCKS + WPREP_BLOCKS) {
        int i = (blk - WSQ_BLOCKS) * 256 + threadIdx.x;
        float4 v = reinterpret_cast<const float4*>(w)[i];
        __half2 p0 = __floats2half2_rn(v.x, v.y), p1 = __floats2half2_rn(v.z, v.w);
        uint2 u;
        u.x = *reinterpret_cast<uint32_t*>(&p0); u.y = *reinterpret_cast<uint32_t*>(&p1);
        reinterpret_cast<uint2*>(g_wh)[i] = u;
    } else {
        int row = (blk - WSQ_BLOCKS - WPREP_BLOCKS) * 8 + (threadIdx.x >> 5);
        int lane = threadIdx.x & 31;
        const float4* src = reinterpret_cast<const float4*>(x + (size_t)row * F_DIM);
        float4 a = src[lane], b = src[lane + 32];
        float s = a.x * a.x + a.y * a.y + a.z * a.z + a.w * a.w
                + b.x * b.x + b.y * b.y + b.z * b.z + b.w * b.w;
#pragma unroll
        for (int o = 16; o > 0; o >>= 1) s += __shfl_down_sync(0xffffffffu, s, o);
        if (lane == 0) g_xsq[row] = s;
        uint2* dst = reinterpret_cast<uint2*>(g_xh + (size_t)row * F_DIM);
        __half2 p0 = __floats2half2_rn(a.x, a.y), p1 = __floats2half2_rn(a.z, a.w);
        __half2 q0 = __floats2half2_rn(b.x, b.y), q1 = __floats2half2_rn(b.z, b.w);
        uint2 u0, u1;
        u0.x = *reinterpret_cast<uint32_t*>(&p0); u0.y = *reinterpret_cast<uint32_t*>(&p1);
        u1.x = *reinterpret_cast<uint32_t*>(&q0); u1.y = *reinterpret_cast<uint32_t*>(&q1);
        dst[lane] = u0; dst[lane + 32] = u1;
    }
}

// ---------------------------------------------------------------- GEMM
__global__ __launch_bounds__(128, 2)
void rbf_gemm_kernel(float* __restrict__ out) {
    extern __shared__ char smem[];
    const uint32_t sb = smem_u32(smem);
    const int tid = threadIdx.x, lane = tid & 31, wi = tid >> 5;  // 4 warps
    const int warp_m = wi & 1, warp_n = wi >> 1;                  // 2x2, tiles 128x64

    const int u_tile = blockIdx.x & 7;          // u fastest -> L2 sharing of x stream
    const int sidx = blockIdx.x >> 3;
    const int u0 = u_tile * UTILE;
    const int b_begin = (sidx * NB_TILES) / NSLICE;
    const int b_end = ((sidx + 1) * NB_TILES) / NSLICE;
    const int C = (b_end - b_begin) * 4;        // 64-wide k-chunks

    if (tid < 32) {
        float4 v = reinterpret_cast<const float4*>(g_wsq + u0)[tid];
        reinterpret_cast<float4*>(smem + SM_WSQ)[tid] = v;
    }

    // chunk loader: A = x[bt*256 .. +256, kc*64 .. +64]  (256 rows x 128B = 32KB)
    //               B = w[kc*64 .. +64, u0 .. +128]      (64 rows x 256B = 16KB)
    auto load_chunk = [&](int c) {
        int slot = c & 1, kc = c & 3, bt = b_begin + (c >> 2);
        uint32_t abuf = sb + SM_A + (uint32_t)(slot * 32768);
        size_t abase = ((size_t)bt * BTILE) * F_DIM + (size_t)kc * 64;
        for (int i = tid; i < 2048; i += 128) {
            int r = i >> 3, cc = i & 7;   // 256 rows x 8 vecs (128B/row)
            cp16(abuf + (uint32_t)(r * 128 + ((cc ^ (r & 7)) << 4)),
                 g_xh + abase + (size_t)r * F_DIM + cc * 8);
        }
        uint32_t bbuf = sb + SM_B + (uint32_t)(slot * 16384);
        const char* bbase = (const char*)(g_wh + (size_t)kc * 64 * U_DIM + u0);
        for (int i = tid; i < 1024; i += 128) {
            int k = i >> 4, cc = i & 15;  // 64 k-rows x 16 vecs (256B/row)
            cp16(bbuf + (uint32_t)(k * 256 + ((cc ^ (k & 7)) << 4)),
                 bbase + (size_t)k * U_DIM * 2 + cc * 16);
        }
        CP_COMMIT();
    };

    load_chunk(0);

    uint32_t acc[8][8][2];   // packed half2 accumulators (128 regs)
    const int lr = lane & 15, lc = lane >> 4;
    const int g = lane >> 2, cq = (lane & 3) * 2;
    const float* ws = reinterpret_cast<const float*>(smem + SM_WSQ);

    for (int c = 0; c < C; c++) {
        const int kc = c & 3, slot = c & 1;
        CP_WAIT(0);               // chunk c fully resident
        __syncthreads();          // cross-thread visibility + c-1 slot free

        if (c + 1 < C) load_chunk(c + 1);   // into the slot consumed at c-1

        if (kc == 0) {
#pragma unroll
            for (int mt = 0; mt < 8; mt++)
#pragma unroll
                for (int nt = 0; nt < 8; nt++) {
                    acc[mt][nt][0] = 0u;
                    acc[mt][nt][1] = 0u;
                }
        }

        // ---- compute chunk c: 64 k, 4 k-steps, warp tile 128x64 ----
        const uint32_t abuf = sb + SM_A + (uint32_t)(slot * 32768);
        const uint32_t bbuf = sb + SM_B + (uint32_t)(slot * 16384);
#pragma unroll
        for (int kk = 0; kk < 64; kk += 16) {
            uint32_t a_frag[8][4];
#pragma unroll
            for (int mt = 0; mt < 8; mt++) {
                int r = warp_m * 128 + mt * 16 + lr;
                int cch = (kk >> 3) + lc;
                uint32_t addr = abuf + (uint32_t)(r * 128 + ((cch ^ (r & 7)) << 4));
                ldm_x4(a_frag[mt][0], a_frag[mt][1], a_frag[mt][2], a_frag[mt][3], addr);
            }
            uint32_t b_frag[8][2];
#pragma unroll
            for (int np = 0; np < 4; np++) {
                int krow = kk + lr;   // within-chunk k row (0..63)
                int cch = warp_n * 8 + np * 2 + lc;   // 16B vec index (0..15)
                uint32_t addr = bbuf + (uint32_t)(krow * 256 + ((cch ^ (krow & 7)) << 4));
                uint32_t r0, r1, r2, r3;
                ldm_x4_t(r0, r1, r2, r3, addr);
                b_frag[np * 2][0] = r0;     b_frag[np * 2][1] = r1;
                b_frag[np * 2 + 1][0] = r2; b_frag[np * 2 + 1][1] = r3;
            }
#pragma unroll
            for (int mt = 0; mt < 8; mt++)
#pragma unroll
                for (int nt = 0; nt < 8; nt++)
                    mma_16816_f16(acc[mt][nt], a_frag[mt], b_frag[nt]);
        }

        // ---- epilogue ----
        if (kc == 3) {
            int bt = b_begin + (c >> 2);
#pragma unroll
            for (int mt = 0; mt < 8; mt++) {
                int rloc = warp_m * 128 + mt * 16 + g;
                float xlo = __ldg(&g_xsq[bt * BTILE + rloc]);
                float xhi = __ldg(&g_xsq[bt * BTILE + rloc + 8]);
                size_t row_lo = (size_t)(bt * BTILE + rloc) * U_DIM;
                size_t row_hi = row_lo + (size_t)8 * U_DIM;
#pragma unroll
                for (int nt = 0; nt < 8; nt++) {
                    int cloc = warp_n * 64 + nt * 8 + cq;   // 0..127
                    float w0 = ws[cloc], w1 = ws[cloc + 1];
                    float2 clo = __half22float2(*reinterpret_cast<__half2*>(&acc[mt][nt][0]));
                    float2 chi = __half22float2(*reinterpret_cast<__half2*>(&acc[mt][nt][1]));
                    float2 vlo, vhi;
                    vlo.x = fmaf(-2.f, clo.x, xlo + w0);
                    vlo.y = fmaf(-2.f, clo.y, xlo + w1);
                    vhi.x = fmaf(-2.f, chi.x, xhi + w0);
                    vhi.y = fmaf(-2.f, chi.y, xhi + w1);
                    __stcs(reinterpret_cast<float2*>(out + row_lo + u0 + cloc), vlo);
                    __stcs(reinterpret_cast<float2*>(out + row_hi + u0 + cloc), vhi);
                }
            }
        }
    }
}

extern "C" void kernel_launch(void* const* d_in, const int* in_sizes, int n_in,
                              void* d_out, int out_size) {
    const float* x = (const float*)d_in[0];
    const float* w = (const float*)d_in[1];
    float* out = (float*)d_out;

    cudaFuncSetAttribute(rbf_gemm_kernel, cudaFuncAttributeMaxDynamicSharedMemorySize, SM_TOT);

    prep_kernel<<<WSQ_BLOCKS + WPREP_BLOCKS + XPREP_BLOCKS, 256>>>(x, w);
    rbf_gemm_kernel<<<GRID_CTAS, 128, SM_TOT>>>(out);
}